// round 12
// baseline (speedup 1.0000x reference)
#include <cuda_runtime.h>
#include <cuda_bf16.h>

// Problem constants (fixed by the dataset)
#define Bsz   32768
#define INF   784
#define Hdim  128
#define OUTD  10
#define NSTEP 25

typedef unsigned long long u64;

// -------- packed f32x2 helpers (Blackwell dual-fp32 pipe) --------
__device__ __forceinline__ u64 fma2(u64 a, u64 b, u64 c) {
    u64 d;
    asm("fma.rn.f32x2 %0, %1, %2, %3;" : "=l"(d) : "l"(a), "l"(b), "l"(c));
    return d;
}
__device__ __forceinline__ u64 pack2(float x, float y) {
    u64 d;
    asm("mov.b64 %0, {%1, %2};" : "=l"(d) : "f"(x), "f"(y));
    return d;
}
__device__ __forceinline__ float2 unpack2(u64 a) {
    float2 r;
    asm("mov.b64 {%0, %1}, %2;" : "=f"(r.x), "=f"(r.y) : "l"(a));
    return r;
}

// -------- device scratch (no allocation allowed) --------
__device__ float    g_cur1[(size_t)Bsz * Hdim];        // 16 MB
__device__ unsigned g_spk[(size_t)NSTEP * Bsz * 4];    // 13.1 MB spike bitmasks

// ============================================================
// gemm1: cur1[b][h] = sum_k x[b][k] * W1[h][k] + b1[h]
// (unchanged from R11 — 128x128 tile, BK=16, on-the-fly W1 transpose,
//  MOV-free inner loop: 12 LDS.64 + 32 FFMA2.)
// Reduction order: single accumulator, ascending-k FMA chain; bias added
// once after full-K reduction (bitwise rel_err 0.0 model).
// ============================================================
__global__ __launch_bounds__(256) void gemm1_kernel(const float* __restrict__ x,
                                                    const float* __restrict__ W1g,
                                                    const float* __restrict__ b1) {
    __shared__ float2 Asd[16][129];   // [k][row] duplicated (a,a)
    __shared__ float  Bs[16][132];    // [k][col], padded
    __shared__ float  b1s[128];

    const int tid = threadIdx.x;
    const int bm = blockIdx.x * 128;

    if (tid < 128) b1s[tid] = b1[tid];

    const int arow = tid >> 2;          // 0..63
    const int acg  = (tid & 3) * 4;     // k sub-offset 0,4,8,12
    const int sk  = tid & 15;           // k within tile (B transpose map)
    const int sc0 = tid >> 4;           // base col 0..15

    const int tx = tid & 15;            // col group (pairs 2tx+32j)
    const int ty = tid >> 4;            // row group (rows ty*8..ty*8+7)

    u64 cp[8][4];
#pragma unroll
    for (int ri = 0; ri < 8; ri++)
#pragma unroll
        for (int j = 0; j < 4; j++) cp[ri][j] = 0ull;

    float4 a0 = *(const float4*)(x + (size_t)(bm + arow) * INF + acg);
    float4 a1 = *(const float4*)(x + (size_t)(bm + arow + 64) * INF + acg);
    float bpre[8];
#pragma unroll
    for (int p = 0; p < 8; p++)
        bpre[p] = W1g[(size_t)(sc0 + 16 * p) * INF + sk];

    const int KITER = INF / 16;  // 49
    for (int t = 0; t < KITER; t++) {
        __syncthreads();
        Asd[acg + 0][arow] = make_float2(a0.x, a0.x);
        Asd[acg + 1][arow] = make_float2(a0.y, a0.y);
        Asd[acg + 2][arow] = make_float2(a0.z, a0.z);
        Asd[acg + 3][arow] = make_float2(a0.w, a0.w);
        Asd[acg + 0][arow + 64] = make_float2(a1.x, a1.x);
        Asd[acg + 1][arow + 64] = make_float2(a1.y, a1.y);
        Asd[acg + 2][arow + 64] = make_float2(a1.z, a1.z);
        Asd[acg + 3][arow + 64] = make_float2(a1.w, a1.w);
#pragma unroll
        for (int p = 0; p < 8; p++)
            Bs[sk][sc0 + 16 * p] = bpre[p];
        __syncthreads();

        if (t < KITER - 1) {
            int k0 = (t + 1) * 16;
            a0 = *(const float4*)(x + (size_t)(bm + arow) * INF + k0 + acg);
            a1 = *(const float4*)(x + (size_t)(bm + arow + 64) * INF + k0 + acg);
#pragma unroll
            for (int p = 0; p < 8; p++)
                bpre[p] = W1g[(size_t)(sc0 + 16 * p) * INF + k0 + sk];
        }

#pragma unroll
        for (int kk = 0; kk < 16; kk++) {
            u64 ap[8];
#pragma unroll
            for (int ri = 0; ri < 8; ri++)
                ap[ri] = *(const u64*)&Asd[kk][ty * 8 + ri];   // broadcast (a,a)
            u64 bp[4];
#pragma unroll
            for (int j = 0; j < 4; j++)
                bp[j] = *(const u64*)&Bs[kk][2 * tx + 32 * j]; // contiguous pair
#pragma unroll
            for (int ri = 0; ri < 8; ri++)
#pragma unroll
                for (int j = 0; j < 4; j++)
                    cp[ri][j] = fma2(ap[ri], bp[j], cp[ri][j]);
        }
    }

#pragma unroll
    for (int ri = 0; ri < 8; ri++) {
        int r = bm + ty * 8 + ri;
        float* orow = g_cur1 + (size_t)r * Hdim;
#pragma unroll
        for (int j = 0; j < 4; j++) {
            int c = 2 * tx + 32 * j;
            float2 v = unpack2(cp[ri][j]);
            float2 s;
            s.x = __fadd_rn(v.x, b1s[c]);
            s.y = __fadd_rn(v.y, b1s[c + 1]);
            *(float2*)&orow[c] = s;
        }
    }
}

// ============================================================
// lif1: layer-1 LIF, fully parallel over (b,h) — the recurrence couples
// only across t, never across h. Thread = one neuron; membrane in ONE
// register; spikes emitted as warp ballots (bit i = h (word*32+i), bits
// ascend with h exactly as layer-2 consumes them).
//   mem = fma(0.9, mem_prev, cur); if (mem_prev > 1) mem -= 1;  (bitwise
//   identical to the rel_err==0.0 model)
// ============================================================
__global__ __launch_bounds__(256) void lif1_kernel() {
    const int tid = blockIdx.x * 256 + threadIdx.x;   // = b*128 + h
    const float c = g_cur1[tid];
    const int b = tid >> 7;
    const int word = (tid >> 5) & 3;
    const int lane = threadIdx.x & 31;

    unsigned* dst = g_spk + (size_t)b * 4 + word;
    float m = 0.0f;
#pragma unroll
    for (int t = 0; t < NSTEP; t++) {
        float mo = m;
        m = __fmaf_rn(0.9f, mo, c);
        if (mo > 1.0f) m = __fadd_rn(m, -1.0f);
        unsigned msk = __ballot_sync(0xffffffffu, m > 1.0f);
        if (lane == 0) dst[(size_t)t * Bsz * 4] = msk;
    }
}

// ============================================================
// lif2: layer-2 LIF + tiny GEMM from spike bitmasks. Thread = one batch
// row; only 8 KB smem/CTA (w2 rows padded to 64B for 2xLDS.128+LDS.64
// broadcast) -> occupancy no longer smem-bound. mem2 = 10 scalars in regs.
// cur2 chain: ascending-h, fma2(spike?1:0, w, acc) — fma2(1,w,acc) rounds
// exactly like fadd_rn(w,acc); fma2(0,w,acc) is exact identity -> the
// spiking-term chain is bit-identical to the reference order.
// ============================================================
__global__ __launch_bounds__(64) void lif2_kernel(const float* __restrict__ W2g,
                                                  const float* __restrict__ b2g,
                                                  float* __restrict__ out) {
    __shared__ u64 w2s[Hdim * 8];    // [h][p], padded to 8 u64 per h (64B)

    const int tid = threadIdx.x;
    const int b = blockIdx.x * 64 + tid;

    // fill w2 pairs (coalesced-ish LDG; trivial one-time cost)
    for (int i = tid; i < Hdim * 5; i += 64) {
        int h = i / 5, p = i - 5 * h;
        w2s[h * 8 + p] = pack2(W2g[(2 * p) * Hdim + h], W2g[(2 * p + 1) * Hdim + h]);
    }
    __syncthreads();

    // b2 pairs into registers (broadcast loads)
    u64 b2p[5];
#pragma unroll
    for (int p = 0; p < 5; p++)
        b2p[p] = *(const u64*)(b2g + 2 * p);

    float m2[OUTD];
#pragma unroll
    for (int o = 0; o < OUTD; o++) m2[o] = 0.0f;

    const unsigned* mbase = g_spk + (size_t)b * 4;
    float* outp = out + (size_t)b * OUTD;

    const u64 ONE2 = 0x3F8000003F800000ull;  // packed (1.0f, 1.0f)

#pragma unroll 1
    for (int t = 0; t < NSTEP; t++) {
        uint4 mk = *(const uint4*)(mbase + (size_t)t * Bsz * 4);
        u64 a0 = 0ull, a1 = 0ull, a2 = 0ull, a3 = 0ull, a4 = 0ull;

#pragma unroll
        for (int w = 0; w < 4; w++) {
            unsigned mw = (w == 0) ? mk.x : (w == 1) ? mk.y : (w == 2) ? mk.z : mk.w;
#pragma unroll
            for (int bit = 0; bit < 32; bit++) {
                int h = w * 32 + bit;
                u64 sp = (mw & (1u << bit)) ? ONE2 : 0ull;   // ISETP + 2 SEL
                const u64* wp = &w2s[h * 8];
                a0 = fma2(sp, wp[0], a0);
                a1 = fma2(sp, wp[1], a1);
                a2 = fma2(sp, wp[2], a2);
                a3 = fma2(sp, wp[3], a3);
                a4 = fma2(sp, wp[4], a4);
            }
        }

        // cu = c2 + b2 (element-wise fadd_rn), then scalar mem2 updates
        u64 cu[5] = {0, 0, 0, 0, 0};
        {
            // fma2(1, acc, b2) == per-element fadd_rn(acc, b2)
            cu[0] = fma2(ONE2, a0, b2p[0]);
            cu[1] = fma2(ONE2, a1, b2p[1]);
            cu[2] = fma2(ONE2, a2, b2p[2]);
            cu[3] = fma2(ONE2, a3, b2p[3]);
            cu[4] = fma2(ONE2, a4, b2p[4]);
        }
        float* op = outp + (size_t)t * Bsz * OUTD;
#pragma unroll
        for (int p = 0; p < 5; p++) {
            float2 c = unpack2(cu[p]);
            float so0, so1;
            {
                float mo = m2[2 * p];
                float m = __fmaf_rn(0.9f, mo, c.x);
                if (mo > 1.0f) m = __fadd_rn(m, -1.0f);
                m2[2 * p] = m;
                so0 = (m > 1.0f) ? 1.0f : 0.0f;
            }
            {
                float mo = m2[2 * p + 1];
                float m = __fmaf_rn(0.9f, mo, c.y);
                if (mo > 1.0f) m = __fadd_rn(m, -1.0f);
                m2[2 * p + 1] = m;
                so1 = (m > 1.0f) ? 1.0f : 0.0f;
            }
            *(float2*)(op + 2 * p) = make_float2(so0, so1);
        }
    }
}

// ============================================================
extern "C" void kernel_launch(void* const* d_in, const int* in_sizes, int n_in,
                              void* d_out, int out_size) {
    (void)in_sizes; (void)n_in; (void)out_size;
    const float* x  = (const float*)d_in[0];
    const float* W1 = (const float*)d_in[1];
    const float* b1 = (const float*)d_in[2];
    const float* W2 = (const float*)d_in[3];
    const float* b2 = (const float*)d_in[4];
    float* out = (float*)d_out;

    gemm1_kernel<<<Bsz / 128, 256>>>(x, W1, b1);
    lif1_kernel<<<(Bsz * Hdim) / 256, 256>>>();
    lif2_kernel<<<Bsz / 64, 64>>>(W2, b2, out);
}

// round 13
// speedup vs baseline: 2.9017x; 2.9017x over previous
#include <cuda_runtime.h>
#include <cuda_bf16.h>

// Problem constants (fixed by the dataset)
#define Bsz   32768
#define INF   784
#define Hdim  128
#define OUTD  10
#define NSTEP 25

typedef unsigned long long u64;

// -------- packed f32x2 helpers (Blackwell dual-fp32 pipe) --------
__device__ __forceinline__ u64 fma2(u64 a, u64 b, u64 c) {
    u64 d;
    asm("fma.rn.f32x2 %0, %1, %2, %3;" : "=l"(d) : "l"(a), "l"(b), "l"(c));
    return d;
}
__device__ __forceinline__ u64 pack2(float x, float y) {
    u64 d;
    asm("mov.b64 %0, {%1, %2};" : "=l"(d) : "f"(x), "f"(y));
    return d;
}
__device__ __forceinline__ float2 unpack2(u64 a) {
    float2 r;
    asm("mov.b64 {%0, %1}, %2;" : "=f"(r.x), "=f"(r.y) : "l"(a));
    return r;
}

// -------- device scratch (no allocation allowed) --------
__device__ float    g_cur1[(size_t)Bsz * Hdim];        // 16 MB
__device__ unsigned g_spk[(size_t)NSTEP * Bsz * 4];    // 13.1 MB spike bitmasks

// ============================================================
// gemm1: UNCHANGED from R11/R12 (known 173us). cur1 = x@W1^T + b1.
// ============================================================
__global__ __launch_bounds__(256) void gemm1_kernel(const float* __restrict__ x,
                                                    const float* __restrict__ W1g,
                                                    const float* __restrict__ b1) {
    __shared__ float2 Asd[16][129];   // [k][row] duplicated (a,a)
    __shared__ float  Bs[16][132];    // [k][col], padded
    __shared__ float  b1s[128];

    const int tid = threadIdx.x;
    const int bm = blockIdx.x * 128;

    if (tid < 128) b1s[tid] = b1[tid];

    const int arow = tid >> 2;          // 0..63
    const int acg  = (tid & 3) * 4;     // k sub-offset 0,4,8,12
    const int sk  = tid & 15;           // k within tile (B transpose map)
    const int sc0 = tid >> 4;           // base col 0..15

    const int tx = tid & 15;            // col group (pairs 2tx+32j)
    const int ty = tid >> 4;            // row group (rows ty*8..ty*8+7)

    u64 cp[8][4];
#pragma unroll
    for (int ri = 0; ri < 8; ri++)
#pragma unroll
        for (int j = 0; j < 4; j++) cp[ri][j] = 0ull;

    float4 a0 = *(const float4*)(x + (size_t)(bm + arow) * INF + acg);
    float4 a1 = *(const float4*)(x + (size_t)(bm + arow + 64) * INF + acg);
    float bpre[8];
#pragma unroll
    for (int p = 0; p < 8; p++)
        bpre[p] = W1g[(size_t)(sc0 + 16 * p) * INF + sk];

    const int KITER = INF / 16;  // 49
    for (int t = 0; t < KITER; t++) {
        __syncthreads();
        Asd[acg + 0][arow] = make_float2(a0.x, a0.x);
        Asd[acg + 1][arow] = make_float2(a0.y, a0.y);
        Asd[acg + 2][arow] = make_float2(a0.z, a0.z);
        Asd[acg + 3][arow] = make_float2(a0.w, a0.w);
        Asd[acg + 0][arow + 64] = make_float2(a1.x, a1.x);
        Asd[acg + 1][arow + 64] = make_float2(a1.y, a1.y);
        Asd[acg + 2][arow + 64] = make_float2(a1.z, a1.z);
        Asd[acg + 3][arow + 64] = make_float2(a1.w, a1.w);
#pragma unroll
        for (int p = 0; p < 8; p++)
            Bs[sk][sc0 + 16 * p] = bpre[p];
        __syncthreads();

        if (t < KITER - 1) {
            int k0 = (t + 1) * 16;
            a0 = *(const float4*)(x + (size_t)(bm + arow) * INF + k0 + acg);
            a1 = *(const float4*)(x + (size_t)(bm + arow + 64) * INF + k0 + acg);
#pragma unroll
            for (int p = 0; p < 8; p++)
                bpre[p] = W1g[(size_t)(sc0 + 16 * p) * INF + k0 + sk];
        }

#pragma unroll
        for (int kk = 0; kk < 16; kk++) {
            u64 ap[8];
#pragma unroll
            for (int ri = 0; ri < 8; ri++)
                ap[ri] = *(const u64*)&Asd[kk][ty * 8 + ri];   // broadcast (a,a)
            u64 bp[4];
#pragma unroll
            for (int j = 0; j < 4; j++)
                bp[j] = *(const u64*)&Bs[kk][2 * tx + 32 * j]; // contiguous pair
#pragma unroll
            for (int ri = 0; ri < 8; ri++)
#pragma unroll
                for (int j = 0; j < 4; j++)
                    cp[ri][j] = fma2(ap[ri], bp[j], cp[ri][j]);
        }
    }

#pragma unroll
    for (int ri = 0; ri < 8; ri++) {
        int r = bm + ty * 8 + ri;
        float* orow = g_cur1 + (size_t)r * Hdim;
#pragma unroll
        for (int j = 0; j < 4; j++) {
            int c = 2 * tx + 32 * j;
            float2 v = unpack2(cp[ri][j]);
            float2 s;
            s.x = __fadd_rn(v.x, b1s[c]);
            s.y = __fadd_rn(v.y, b1s[c + 1]);
            *(float2*)&orow[c] = s;
        }
    }
}

// ============================================================
// lif1: UNCHANGED from R12. Layer-1 LIF, thread = (b,h), membrane in one
// register, spikes emitted as warp ballots (bit i of word w = h = 32w+i).
// ============================================================
__global__ __launch_bounds__(256) void lif1_kernel() {
    const int tid = blockIdx.x * 256 + threadIdx.x;   // = b*128 + h
    const float c = g_cur1[tid];
    const int b = tid >> 7;
    const int word = (tid >> 5) & 3;
    const int lane = threadIdx.x & 31;

    unsigned* dst = g_spk + (size_t)b * 4 + word;
    float m = 0.0f;
#pragma unroll
    for (int t = 0; t < NSTEP; t++) {
        float mo = m;
        m = __fmaf_rn(0.9f, mo, c);
        if (mo > 1.0f) m = __fadd_rn(m, -1.0f);
        unsigned msk = __ballot_sync(0xffffffffu, m > 1.0f);
        if (lane == 0) dst[(size_t)t * Bsz * 4] = msk;
    }
}

// ============================================================
// lif2: layer-2 LIF + tiny GEMM from spike bitmasks.
// TWO threads per batch row (parity q handles outputs 5q..5q+4) ->
// 65536 threads = 2048 warps = 3.46 warps/SMSP (2x the fused snn's hiding).
// Per h: 2 ALU (mw&1 -> pred, mw>>=1) + 2 SEL + LDS.128 + LDS.64 + 3 fma2
// ~= 9 issue slots. Inner loop unroll 8 -> ~1.5KB body, I$-L0 resident.
// Each scalar output keeps its exact ascending-h fma2(spike,w,acc) chain:
// fma2(0,w,acc) is an exact identity, fma2(1,w,acc) rounds as fadd_rn ->
// bitwise identical to the rel_err==0.0 model. b2 added once after the
// reduction via fma2(ONE2, acc, b2) == element-wise fadd_rn.
//
// w2q smem layout [q][h][4] u64 (32B/h -> LDS.128 + LDS.64):
//   j0 = (W2[5q][h],   W2[5q+1][h])
//   j1 = (W2[5q+2][h], W2[5q+3][h])
//   j2 = (W2[5q+4][h], 0)            (dummy lane stays exactly 0)
// ============================================================
__global__ __launch_bounds__(128) void lif2_kernel(const float* __restrict__ W2g,
                                                   const float* __restrict__ b2g,
                                                   float* __restrict__ out) {
    __shared__ u64 w2q[2][Hdim][4];   // 8 KB

    const int tid = threadIdx.x;
    const int q = tid & 1;                    // output-half parity
    const int b = blockIdx.x * 64 + (tid >> 1);

    // one-time w2 repack: i indexes (qq, h)
    for (int i = tid; i < 2 * Hdim; i += 128) {
        int qq = i >> 7;
        int h  = i & 127;
        int o0 = qq * 5;
        w2q[qq][h][0] = pack2(W2g[(o0 + 0) * Hdim + h], W2g[(o0 + 1) * Hdim + h]);
        w2q[qq][h][1] = pack2(W2g[(o0 + 2) * Hdim + h], W2g[(o0 + 3) * Hdim + h]);
        w2q[qq][h][2] = pack2(W2g[(o0 + 4) * Hdim + h], 0.0f);
        w2q[qq][h][3] = 0ull;
    }
    __syncthreads();

    // b2 pairs for this parity (broadcast LDG)
    u64 b2p0 = pack2(b2g[q * 5 + 0], b2g[q * 5 + 1]);
    u64 b2p1 = pack2(b2g[q * 5 + 2], b2g[q * 5 + 3]);
    u64 b2p2 = pack2(b2g[q * 5 + 4], 0.0f);

    float m2a = 0.0f, m2b = 0.0f, m2c = 0.0f, m2d = 0.0f, m2e = 0.0f;

    const unsigned* mbase = g_spk + (size_t)b * 4;
    float* outp = out + (size_t)b * OUTD + q * 5;
    const u64* wbase = &w2q[q][0][0];

    const u64 ONE2 = 0x3F8000003F800000ull;  // packed (1.0f, 1.0f)

#pragma unroll 1
    for (int t = 0; t < NSTEP; t++) {
        uint4 mk = *(const uint4*)(mbase + (size_t)t * Bsz * 4);
        u64 a0 = 0ull, a1 = 0ull, a2 = 0ull;

#pragma unroll
        for (int w = 0; w < 4; w++) {
            unsigned mw = (w == 0) ? mk.x : (w == 1) ? mk.y : (w == 2) ? mk.z : mk.w;
            const u64* wp = wbase + (w * 32) * 4;
#pragma unroll 8
            for (int bit = 0; bit < 32; bit++) {
                u64 sp = (mw & 1u) ? ONE2 : 0ull;   // LOP3.pred + 2 SEL
                mw >>= 1;
                a0 = fma2(sp, wp[0], a0);
                a1 = fma2(sp, wp[1], a1);
                a2 = fma2(sp, wp[2], a2);
                wp += 4;
            }
        }

        // cu = acc + b2 (element-wise fadd_rn via fma2(1, acc, b2))
        u64 cu0 = fma2(ONE2, a0, b2p0);
        u64 cu1 = fma2(ONE2, a1, b2p1);
        u64 cu2 = fma2(ONE2, a2, b2p2);

        float2 c01 = unpack2(cu0);
        float2 c23 = unpack2(cu1);
        float2 c4x = unpack2(cu2);

        float* op = outp + (size_t)t * Bsz * OUTD;
        // 5 scalar LIF updates (exact FFMA + predicated subtract model)
        {
            float mo = m2a;
            float m = __fmaf_rn(0.9f, mo, c01.x);
            if (mo > 1.0f) m = __fadd_rn(m, -1.0f);
            m2a = m; op[0] = (m > 1.0f) ? 1.0f : 0.0f;
        }
        {
            float mo = m2b;
            float m = __fmaf_rn(0.9f, mo, c01.y);
            if (mo > 1.0f) m = __fadd_rn(m, -1.0f);
            m2b = m; op[1] = (m > 1.0f) ? 1.0f : 0.0f;
        }
        {
            float mo = m2c;
            float m = __fmaf_rn(0.9f, mo, c23.x);
            if (mo > 1.0f) m = __fadd_rn(m, -1.0f);
            m2c = m; op[2] = (m > 1.0f) ? 1.0f : 0.0f;
        }
        {
            float mo = m2d;
            float m = __fmaf_rn(0.9f, mo, c23.y);
            if (mo > 1.0f) m = __fadd_rn(m, -1.0f);
            m2d = m; op[3] = (m > 1.0f) ? 1.0f : 0.0f;
        }
        {
            float mo = m2e;
            float m = __fmaf_rn(0.9f, mo, c4x.x);
            if (mo > 1.0f) m = __fadd_rn(m, -1.0f);
            m2e = m; op[4] = (m > 1.0f) ? 1.0f : 0.0f;
        }
    }
}

// ============================================================
extern "C" void kernel_launch(void* const* d_in, const int* in_sizes, int n_in,
                              void* d_out, int out_size) {
    (void)in_sizes; (void)n_in; (void)out_size;
    const float* x  = (const float*)d_in[0];
    const float* W1 = (const float*)d_in[1];
    const float* b1 = (const float*)d_in[2];
    const float* W2 = (const float*)d_in[3];
    const float* b2 = (const float*)d_in[4];
    float* out = (float*)d_out;

    gemm1_kernel<<<Bsz / 128, 256>>>(x, W1, b1);
    lif1_kernel<<<(Bsz * Hdim) / 256, 256>>>();
    lif2_kernel<<<Bsz / 64, 128>>>(W2, b2, out);
}